// round 11
// baseline (speedup 1.0000x reference)
#include <cuda_runtime.h>
#include <cstdint>
#include <cstddef>

#define BB 8
#define TT 2048
#define CC 1024
#define HH 128

// Scratch (device globals — no runtime alloc).
__device__ float g_q[BB * TT * HH];   // d-interleaved layout
__device__ float g_k[BB * TT * HH];   // d-interleaved layout
__device__ float g_v[BB * TT * HH];   // natural layout
// GEMM K-split partials: [khalf][proj*128+mblk][128*128] raw fp32.
__device__ float g_gp[2][3 * 128 * 16384 / 128];   // 2 x 393216... see index math
// (flat: [khalf][ (proj*128+mblk)*16384 + e ])
__device__ float g_gp2[2][3 * 128 * 16384 - 3 * 128 * 16384 / 128 * 1];  // unused pad guard
// Split-KV partials: [part][(qt-16)*8+b][64*128] unnormalized O; m,l per row.
__device__ float g_po[2][128][64 * 128];
__device__ float g_pm[2][128][64];
__device__ float g_pl[2][128][64];

// Proper-sized GEMM partial buffers (the two above were a sizing slip; use these).
__device__ float g_p0[3 * 128 * 16384];
__device__ float g_p1[3 * 128 * 16384];

// Attention job table, LPT order (descending KV-tile count).
// part: 0 = KV[0,h), 1 = KV[h,qt+1), 2 = full; h = (qt+1)>>1.
__constant__ signed char c_qt[48] = {
    31,31,30,15,30,29,29,28,14,28,27,27,26,13,26,25,25,24,12,24,
    23,23,22,11,22,21,21,20,10,20,19,19,18, 9,18,17,17,16, 8,16,
     7, 6, 5, 4, 3, 2, 1, 0 };
__constant__ signed char c_part[48] = {
     0, 1, 1, 2, 0, 0, 1, 1, 2, 0, 0, 1, 1, 2, 0, 0, 1, 1, 2, 0,
     0, 1, 1, 2, 0, 0, 1, 1, 2, 0, 0, 1, 1, 2, 0, 0, 1, 1, 2, 0,
     2, 2, 2, 2, 2, 2, 2, 2 };

// ---------------------------------------------------------------------------
// Helpers
// ---------------------------------------------------------------------------
__device__ __forceinline__ float tf32r(float x) {
    uint32_t u;
    asm("cvt.rna.tf32.f32 %0, %1;" : "=r"(u) : "f"(x));
    return __uint_as_float(u);
}
__device__ __forceinline__ uint32_t tf32u(float x) {
    uint32_t u;
    asm("cvt.rna.tf32.f32 %0, %1;" : "=r"(u) : "f"(x));
    return u;
}
__device__ __forceinline__ void cp16(uint32_t saddr, const float* gaddr) {
    asm volatile("cp.async.cg.shared.global [%0], [%1], 16;"
                 :: "r"(saddr), "l"(gaddr));
}
__device__ __forceinline__ void cp_commit() {
    asm volatile("cp.async.commit_group;");
}
__device__ __forceinline__ float fex2(float x) {
    float r;
    asm("ex2.approx.f32 %0, %1;" : "=f"(r) : "f"(x));
    return r;
}
__device__ __forceinline__ void mma8(float* c, const uint32_t* a,
                                     uint32_t b0, uint32_t b1) {
    asm volatile(
        "mma.sync.aligned.m16n8k8.row.col.f32.tf32.tf32.f32 "
        "{%0,%1,%2,%3}, {%4,%5,%6,%7}, {%8,%9}, {%0,%1,%2,%3};"
        : "+f"(c[0]), "+f"(c[1]), "+f"(c[2]), "+f"(c[3])
        : "r"(a[0]), "r"(a[1]), "r"(a[2]), "r"(a[3]), "r"(b0), "r"(b1));
}

// ---------------------------------------------------------------------------
// QKV projection GEMM, tf32 mma.sync, K-split x2.
// Grid (3, 128, 2): proj, mblk, khalf. Each CTA: 128x128 tile over K=512,
// writes raw fp32 partial. 128 thr = 4 warps of 64x64, 3-stage cp.async.
// ---------------------------------------------------------------------------
#define AST 36
#define BST 136
#define A_FL (128 * AST)
#define B_FL (32 * BST)
#define STG_FL (A_FL + B_FL)
#define NCHUNK 16

__global__ __launch_bounds__(128, 2) void qkv_mma_kernel(
    const float* __restrict__ X,
    const float* __restrict__ Wq,
    const float* __restrict__ Wk,
    const float* __restrict__ Wv)
{
    extern __shared__ float smem[];

    const int proj  = blockIdx.x;
    const int mblk  = blockIdx.y;
    const int khalf = blockIdx.z;
    const int kbase = khalf * NCHUNK;
    const float* __restrict__ W = (proj == 0) ? Wq : (proj == 1) ? Wk : Wv;
    float* __restrict__ part = (khalf ? g_p1 : g_p0) + ((size_t)(proj * 128 + mblk)) * 16384;

    const int tid  = threadIdx.x;
    const int wid  = tid >> 5;
    const int lane = tid & 31;
    const int g    = lane >> 2;
    const int tg   = lane & 3;
    const int wm   = wid & 1;
    const int wn   = wid >> 1;

    const uint32_t smema = (uint32_t)__cvta_generic_to_shared(smem);
    const float* Xb = X + (size_t)mblk * 128 * CC;

    auto issue_chunk = [&](int kc) {
        const int kg = kbase + kc;
        const uint32_t sAa = smema + (uint32_t)((kc % 3) * STG_FL) * 4;
        const uint32_t sBa = sAa + A_FL * 4;
#pragma unroll
        for (int it = 0; it < 8; it++) {
            int f  = tid + it * 128;
            int r  = f >> 3;
            int c4 = f & 7;
            cp16(sAa + (r * AST + c4 * 4) * 4, Xb + (size_t)r * CC + kg * 32 + c4 * 4);
        }
#pragma unroll
        for (int it = 0; it < 8; it++) {
            int f  = tid + it * 128;
            int r  = f >> 5;
            int c4 = f & 31;
            cp16(sBa + (r * BST + c4 * 4) * 4, W + (size_t)(kg * 32 + r) * HH + c4 * 4);
        }
        cp_commit();
    };

    float acc[4][8][4];
#pragma unroll
    for (int i = 0; i < 4; i++)
#pragma unroll
        for (int n = 0; n < 8; n++)
#pragma unroll
            for (int v = 0; v < 4; v++) acc[i][n][v] = 0.0f;

    issue_chunk(0);
    issue_chunk(1);

    for (int kc = 0; kc < NCHUNK; kc++) {
        if (kc < NCHUNK - 1) asm volatile("cp.async.wait_group 1;");
        else                 asm volatile("cp.async.wait_group 0;");
        __syncthreads();
        if (kc + 2 < NCHUNK) issue_chunk(kc + 2);

        const float* aB = smem + (kc % 3) * STG_FL;
        const float* bB = aB + A_FL;

#pragma unroll
        for (int ks = 0; ks < 4; ks++) {
            uint32_t af[4][4];
#pragma unroll
            for (int i = 0; i < 4; i++) {
                const int base = (wm * 64 + i * 16 + g) * AST + ks * 8 + tg;
                af[i][0] = tf32u(aB[base]);
                af[i][1] = tf32u(aB[base + 8 * AST]);
                af[i][2] = tf32u(aB[base + 4]);
                af[i][3] = tf32u(aB[base + 8 * AST + 4]);
            }
#pragma unroll
            for (int n = 0; n < 8; n++) {
                const int base = (ks * 8 + tg) * BST + wn * 64 + n * 8 + g;
                uint32_t b0 = tf32u(bB[base]);
                uint32_t b1 = tf32u(bB[base + 4 * BST]);
#pragma unroll
                for (int i = 0; i < 4; i++)
                    mma8(acc[i][n], af[i], b0, b1);
            }
        }
    }

    // Epilogue: raw fp32 partial, natural layout.
#pragma unroll
    for (int i = 0; i < 4; i++) {
        const int r0 = wm * 64 + i * 16 + g;
#pragma unroll
        for (int n = 0; n < 8; n++) {
            const int gbase = wn * 64 + n * 8;
            *(float2*)(part + (size_t)r0 * 128 + gbase + 2 * tg) =
                make_float2(acc[i][n][0], acc[i][n][1]);
            *(float2*)(part + (size_t)(r0 + 8) * 128 + gbase + 2 * tg) =
                make_float2(acc[i][n][2], acc[i][n][3]);
        }
    }
}

// ---------------------------------------------------------------------------
// GEMM combine: out = interleave(tf32r(p0 + p1)). Grid (3, 128), 256 thr.
// q/k get the d-interleave (within 8-group, out col c reads old col
// (c&1) ? (c>>1 within group)+4 : (c>>1)); v is natural.
// ---------------------------------------------------------------------------
__global__ __launch_bounds__(256) void gemm_combine_kernel()
{
    const int proj = blockIdx.x;
    const int mblk = blockIdx.y;
    const float* p0 = g_p0 + ((size_t)(proj * 128 + mblk)) * 16384;
    const float* p1 = g_p1 + ((size_t)(proj * 128 + mblk)) * 16384;
    float* outb = ((proj == 0) ? g_q : (proj == 1) ? g_k : g_v)
                  + (size_t)mblk * 128 * HH;
    const int tid = threadIdx.x;

#pragma unroll
    for (int it = 0; it < 16; it++) {
        int f  = tid + it * 256;          // 4096 float4 outputs
        int r  = f >> 5;
        int j4 = (f & 31) * 4;
        float vals[4];
#pragma unroll
        for (int e = 0; e < 4; e++) {
            int c = j4 + e;
            int o;
            if (proj < 2) {
                int ci = c & 7;
                o = (c & ~7) | ((c & 1) ? ((ci >> 1) + 4) : (ci >> 1));
            } else {
                o = c;
            }
            vals[e] = tf32r(p0[(size_t)r * 128 + o] + p1[(size_t)r * 128 + o]);
        }
        *(float4*)(outb + (size_t)r * HH + j4) =
            make_float4(vals[0], vals[1], vals[2], vals[3]);
    }
}

// ---------------------------------------------------------------------------
// Causal flash attention, split-KV, tf32 mma.sync, 2 CTAs/SM, LPT schedule.
// ---------------------------------------------------------------------------
#define KST 136
#define VST 136

__global__ __launch_bounds__(128, 2) void attn_mma_kernel(float* __restrict__ Out)
{
    extern __shared__ float smem_f[];
    float* sQ = smem_f;
    float* sK = sQ + 64 * KST;
    float* sV = sK + 64 * KST;

    const int slot = blockIdx.x >> 3;
    const int b    = blockIdx.x & 7;
    const int qt   = c_qt[slot];
    const int part = c_part[slot];
    const int h    = (qt + 1) >> 1;
    const int j0   = (part == 1) ? h : 0;
    const int j1   = (part == 0) ? h : (qt + 1);

    const int tid  = threadIdx.x;
    const int wid  = tid >> 5;
    const int lane = tid & 31;
    const int g    = lane >> 2;
    const int tg   = lane & 3;

    const uint32_t sQa = (uint32_t)__cvta_generic_to_shared(sQ);
    const uint32_t sKa = (uint32_t)__cvta_generic_to_shared(sK);
    const uint32_t sVa = (uint32_t)__cvta_generic_to_shared(sV);

    const float* Qb = g_q + ((size_t)b * TT + (size_t)qt * 64) * HH;
    const float* Kb = g_k + ((size_t)b * TT + (size_t)j0 * 64) * HH;
    const float* Vb = g_v + ((size_t)b * TT + (size_t)j0 * 64) * HH;

#pragma unroll
    for (int it = 0; it < 16; it++) {
        int f  = tid + it * 128;
        int r  = f >> 5;
        int c4 = f & 31;
        cp16(sQa + (r * KST + c4 * 4) * 4, Qb + r * HH + c4 * 4);
        cp16(sKa + (r * KST + c4 * 4) * 4, Kb + r * HH + c4 * 4);
    }
    cp_commit();
#pragma unroll
    for (int it = 0; it < 16; it++) {
        int f  = tid + it * 128;
        int r  = f >> 5;
        int c4 = f & 31;
        cp16(sVa + (r * VST + c4 * 4) * 4, Vb + r * HH + c4 * 4);
    }
    cp_commit();

    asm volatile("cp.async.wait_group 1;");
    __syncthreads();

    uint32_t qa[16][4];
#pragma unroll
    for (int ks = 0; ks < 16; ks++) {
        const float* qrow = sQ + (16 * wid + g) * KST + ks * 8 + 2 * tg;
        float2 f0 = *(const float2*)qrow;
        float2 f1 = *(const float2*)(qrow + 8 * KST);
        qa[ks][0] = __float_as_uint(f0.x);
        qa[ks][1] = __float_as_uint(f1.x);
        qa[ks][2] = __float_as_uint(f0.y);
        qa[ks][3] = __float_as_uint(f1.y);
    }

    float o[16][4];
#pragma unroll
    for (int n = 0; n < 16; n++)
#pragma unroll
        for (int v = 0; v < 4; v++) o[n][v] = 0.0f;
    float m0 = -1e30f, m1 = -1e30f, l0 = 0.0f, l1 = 0.0f;

    const float SCL = 0.08838834764831845f * 1.4426950408889634f;
    const int src0 = (lane & ~3) | (tg >> 1);
    const int src1 = src0 + 2;
    const bool odd = (tg & 1);

    for (int j = j0; j < j1; j++) {
        if (j > j0) {
            asm volatile("cp.async.wait_group 1;");
            __syncthreads();
        }

        float c[8][4];
#pragma unroll
        for (int n = 0; n < 8; n++)
#pragma unroll
            for (int v = 0; v < 4; v++) c[n][v] = 0.0f;

#pragma unroll
        for (int ks = 0; ks < 16; ks++) {
#pragma unroll
            for (int n = 0; n < 8; n++) {
                float2 kf = *(const float2*)&sK[(n * 8 + g) * KST + ks * 8 + 2 * tg];
                mma8(c[n], qa[ks], __float_as_uint(kf.x), __float_as_uint(kf.y));
            }
        }

        __syncthreads();
        if (j + 1 < j1) {
            const float* Kn = g_k + ((size_t)b * TT + (size_t)(j + 1) * 64) * HH;
#pragma unroll
            for (int it = 0; it < 16; it++) {
                int f  = tid + it * 128;
                int r  = f >> 5;
                int c4 = f & 31;
                cp16(sKa + (r * KST + c4 * 4) * 4, Kn + r * HH + c4 * 4);
            }
            cp_commit();
        }

#pragma unroll
        for (int n = 0; n < 8; n++)
#pragma unroll
            for (int v = 0; v < 4; v++) c[n][v] *= SCL;

        if (j == qt) {
            const int r0 = 16 * wid + g;
            const int r1 = r0 + 8;
#pragma unroll
            for (int n = 0; n < 8; n++) {
                const int col = 8 * n + 2 * tg;
                if (col     > r0) c[n][0] = -1e30f;
                if (col + 1 > r0) c[n][1] = -1e30f;
                if (col     > r1) c[n][2] = -1e30f;
                if (col + 1 > r1) c[n][3] = -1e30f;
            }
        }

        float rm0 = -1e30f, rm1 = -1e30f;
#pragma unroll
        for (int n = 0; n < 8; n++) {
            rm0 = fmaxf(rm0, fmaxf(c[n][0], c[n][1]));
            rm1 = fmaxf(rm1, fmaxf(c[n][2], c[n][3]));
        }
        rm0 = fmaxf(rm0, __shfl_xor_sync(0xffffffffu, rm0, 1));
        rm0 = fmaxf(rm0, __shfl_xor_sync(0xffffffffu, rm0, 2));
        rm1 = fmaxf(rm1, __shfl_xor_sync(0xffffffffu, rm1, 1));
        rm1 = fmaxf(rm1, __shfl_xor_sync(0xffffffffu, rm1, 2));

        const float m0n = fmaxf(m0, rm0);
        const float m1n = fmaxf(m1, rm1);
        const float a0  = fex2(m0 - m0n);
        const float a1  = fex2(m1 - m1n);

        float rs0 = 0.0f, rs1 = 0.0f;
#pragma unroll
        for (int n = 0; n < 8; n++) {
            c[n][0] = fex2(c[n][0] - m0n);
            c[n][1] = fex2(c[n][1] - m0n);
            c[n][2] = fex2(c[n][2] - m1n);
            c[n][3] = fex2(c[n][3] - m1n);
            rs0 += c[n][0] + c[n][1];
            rs1 += c[n][2] + c[n][3];
        }
        rs0 += __shfl_xor_sync(0xffffffffu, rs0, 1);
        rs0 += __shfl_xor_sync(0xffffffffu, rs0, 2);
        rs1 += __shfl_xor_sync(0xffffffffu, rs1, 1);
        rs1 += __shfl_xor_sync(0xffffffffu, rs1, 2);

        l0 = l0 * a0 + rs0;
        l1 = l1 * a1 + rs1;
        m0 = m0n;
        m1 = m1n;

#pragma unroll
        for (int n = 0; n < 16; n++) {
            o[n][0] *= a0; o[n][1] *= a0;
            o[n][2] *= a1; o[n][3] *= a1;
        }

#pragma unroll
        for (int n = 0; n < 8; n++)
#pragma unroll
            for (int v = 0; v < 4; v++) c[n][v] = tf32r(c[n][v]);

        if (j + 1 < j1) asm volatile("cp.async.wait_group 1;");
        else            asm volatile("cp.async.wait_group 0;");
        __syncthreads();

#pragma unroll
        for (int kk = 0; kk < 8; kk++) {
            float v00 = __shfl_sync(0xffffffffu, c[kk][0], src0);
            float v01 = __shfl_sync(0xffffffffu, c[kk][1], src0);
            float v10 = __shfl_sync(0xffffffffu, c[kk][2], src0);
            float v11 = __shfl_sync(0xffffffffu, c[kk][3], src0);
            float v20 = __shfl_sync(0xffffffffu, c[kk][0], src1);
            float v21 = __shfl_sync(0xffffffffu, c[kk][1], src1);
            float v30 = __shfl_sync(0xffffffffu, c[kk][2], src1);
            float v31 = __shfl_sync(0xffffffffu, c[kk][3], src1);
            uint32_t pa[4];
            pa[0] = __float_as_uint(odd ? v01 : v00);
            pa[1] = __float_as_uint(odd ? v11 : v10);
            pa[2] = __float_as_uint(odd ? v21 : v20);
            pa[3] = __float_as_uint(odd ? v31 : v30);
#pragma unroll
            for (int n = 0; n < 16; n++) {
                const int base = (kk * 8 + tg) * VST + 8 * n + g;
                uint32_t b0 = __float_as_uint(sV[base]);
                uint32_t b1 = __float_as_uint(sV[base + 4 * VST]);
                mma8(o[n], pa, b0, b1);
            }
        }

        __syncthreads();
        if (j + 1 < j1) {
            const float* Vn = g_v + ((size_t)b * TT + (size_t)(j + 1) * 64) * HH;
#pragma unroll
            for (int it = 0; it < 16; it++) {
                int f  = tid + it * 128;
                int r  = f >> 5;
                int c4 = f & 31;
                cp16(sVa + (r * VST + c4 * 4) * 4, Vn + r * HH + c4 * 4);
            }
            cp_commit();
        }
    }

    // ----- epilogue -----
    const int r0 = 16 * wid + g;
    if (part == 2) {
        const float inv0 = 1.0f / l0;
        const float inv1 = 1.0f / l1;
        float* p0 = Out + ((size_t)b * TT + qt * 64 + r0) * HH;
        float* p1 = p0 + 8 * HH;
#pragma unroll
        for (int n = 0; n < 16; n++) {
            const int col = 8 * n + 2 * tg;
            *(float2*)(p0 + col) = make_float2(o[n][0] * inv0, o[n][1] * inv0);
            *(float2*)(p1 + col) = make_float2(o[n][2] * inv1, o[n][3] * inv1);
        }
    } else {
        const int pidx = (qt - 16) * 8 + b;
        float* p0 = g_po[part][pidx] + r0 * 128;
        float* p1 = p0 + 8 * 128;
#pragma unroll
        for (int n = 0; n < 16; n++) {
            const int col = 8 * n + 2 * tg;
            *(float2*)(p0 + col) = make_float2(o[n][0], o[n][1]);
            *(float2*)(p1 + col) = make_float2(o[n][2], o[n][3]);
        }
        if (tg == 0) {
            g_pm[part][pidx][r0]     = m0;
            g_pm[part][pidx][r0 + 8] = m1;
            g_pl[part][pidx][r0]     = l0;
            g_pl[part][pidx][r0 + 8] = l1;
        }
    }
}

// ---------------------------------------------------------------------------
// Combine split-KV partials.
// ---------------------------------------------------------------------------
__global__ __launch_bounds__(256) void combine_kernel(float* __restrict__ Out)
{
    const int idx = blockIdx.x;
    const int qt  = 16 + (idx >> 3);
    const int b   = idx & 7;
    const int tid = threadIdx.x;

    const float* O0 = g_po[0][idx];
    const float* O1 = g_po[1][idx];
    const float* M0 = g_pm[0][idx];
    const float* M1 = g_pm[1][idx];
    const float* L0 = g_pl[0][idx];
    const float* L1 = g_pl[1][idx];
    float* dst = Out + ((size_t)b * TT + (size_t)qt * 64) * HH;

#pragma unroll
    for (int it = 0; it < 8; it++) {
        int f  = tid + it * 256;
        int r  = f >> 5;
        int c4 = f & 31;
        float m0v = M0[r], m1v = M1[r];
        float mv  = fmaxf(m0v, m1v);
        float w0  = fex2(m0v - mv);
        float w1  = fex2(m1v - mv);
        float inv = 1.0f / (L0[r] * w0 + L1[r] * w1);
        float4 a  = *(const float4*)(O0 + r * 128 + c4 * 4);
        float4 bb = *(const float4*)(O1 + r * 128 + c4 * 4);
        float4 res = make_float4((a.x * w0 + bb.x * w1) * inv,
                                 (a.y * w0 + bb.y * w1) * inv,
                                 (a.z * w0 + bb.z * w1) * inv,
                                 (a.w * w0 + bb.w * w1) * inv);
        *(float4*)(dst + r * 128 + c4 * 4) = res;
    }
}

// ---------------------------------------------------------------------------
extern "C" void kernel_launch(void* const* d_in, const int* in_sizes, int n_in,
                              void* d_out, int out_size)
{
    const float* x  = (const float*)d_in[0];
    const float* Wq = (const float*)d_in[1];
    const float* Wk = (const float*)d_in[2];
    const float* Wv = (const float*)d_in[3];
    float* out = (float*)d_out;

    (void)in_sizes; (void)n_in; (void)out_size;

    const int gemm_smem = 3 * STG_FL * (int)sizeof(float);
    cudaFuncSetAttribute(qkv_mma_kernel,
                         cudaFuncAttributeMaxDynamicSharedMemorySize, gemm_smem);
    qkv_mma_kernel<<<dim3(3, (BB * TT) / 128, 2), 128, gemm_smem>>>(x, Wq, Wk, Wv);

    gemm_combine_kernel<<<dim3(3, (BB * TT) / 128), 256>>>();

    const int attn_smem = 64 * (2 * KST + VST) * (int)sizeof(float);
    cudaFuncSetAttribute(attn_mma_kernel,
                         cudaFuncAttributeMaxDynamicSharedMemorySize, attn_smem);
    attn_mma_kernel<<<384, 128, attn_smem>>>(out);

    combine_kernel<<<128, 256>>>(out);
}

// round 12
// speedup vs baseline: 1.0789x; 1.0789x over previous
#include <cuda_runtime.h>
#include <cstdint>
#include <cstddef>

#define BB 8
#define TT 2048
#define CC 1024
#define HH 128

// Scratch (device globals — no runtime alloc).
__device__ float g_q[BB * TT * HH];   // d-interleaved layout
__device__ float g_k[BB * TT * HH];   // d-interleaved layout
__device__ float g_v[BB * TT * HH];   // natural layout
// Split-KV partials: [part][(qt-16)*8+b][64*128] unnormalized O; m,l per row.
__device__ float g_po[2][128][64 * 128];
__device__ float g_pm[2][128][64];
__device__ float g_pl[2][128][64];

// Attention job table, LPT order (descending KV-tile count).
// part: 0 = KV[0,h), 1 = KV[h,qt+1), 2 = full; h = (qt+1)>>1.
__constant__ signed char c_qt[48] = {
    31,31,30,15,30,29,29,28,14,28,27,27,26,13,26,25,25,24,12,24,
    23,23,22,11,22,21,21,20,10,20,19,19,18, 9,18,17,17,16, 8,16,
     7, 6, 5, 4, 3, 2, 1, 0 };
__constant__ signed char c_part[48] = {
     0, 1, 1, 2, 0, 0, 1, 1, 2, 0, 0, 1, 1, 2, 0, 0, 1, 1, 2, 0,
     0, 1, 1, 2, 0, 0, 1, 1, 2, 0, 0, 1, 1, 2, 0, 0, 1, 1, 2, 0,
     2, 2, 2, 2, 2, 2, 2, 2 };

// ---------------------------------------------------------------------------
// Helpers
// ---------------------------------------------------------------------------
__device__ __forceinline__ float tf32r(float x) {
    uint32_t u;
    asm("cvt.rna.tf32.f32 %0, %1;" : "=r"(u) : "f"(x));
    return __uint_as_float(u);
}
__device__ __forceinline__ uint32_t tf32u(float x) {
    uint32_t u;
    asm("cvt.rna.tf32.f32 %0, %1;" : "=r"(u) : "f"(x));
    return u;
}
__device__ __forceinline__ void cp16(uint32_t saddr, const float* gaddr) {
    asm volatile("cp.async.cg.shared.global [%0], [%1], 16;"
                 :: "r"(saddr), "l"(gaddr));
}
__device__ __forceinline__ void cp_commit() {
    asm volatile("cp.async.commit_group;");
}
__device__ __forceinline__ float fex2(float x) {
    float r;
    asm("ex2.approx.f32 %0, %1;" : "=f"(r) : "f"(x));
    return r;
}
__device__ __forceinline__ void mma8(float* c, const uint32_t* a,
                                     uint32_t b0, uint32_t b1) {
    asm volatile(
        "mma.sync.aligned.m16n8k8.row.col.f32.tf32.tf32.f32 "
        "{%0,%1,%2,%3}, {%4,%5,%6,%7}, {%8,%9}, {%0,%1,%2,%3};"
        : "+f"(c[0]), "+f"(c[1]), "+f"(c[2]), "+f"(c[3])
        : "r"(a[0]), "r"(a[1]), "r"(a[2]), "r"(a[3]), "r"(b0), "r"(b1));
}

// ---------------------------------------------------------------------------
// QKV projection GEMM, tf32 mma.sync, 3-stage cp.async pipeline, 1 sync/chunk.
// CTA 128x128, BK=32, 128 thr = 4 warps of 64x64. Grid (3, 128).
// Epilogue writes q/k d-interleaved (per 8-group: [0,4,1,5,2,6,3,7]).
// ---------------------------------------------------------------------------
#define AST 36
#define BST 136
#define A_FL (128 * AST)
#define B_FL (32 * BST)
#define STG_FL (A_FL + B_FL)

__global__ __launch_bounds__(128, 2) void qkv_mma_kernel(
    const float* __restrict__ X,
    const float* __restrict__ Wq,
    const float* __restrict__ Wk,
    const float* __restrict__ Wv)
{
    extern __shared__ float smem[];

    const int proj = blockIdx.x;
    const int mblk = blockIdx.y;
    const float* __restrict__ W = (proj == 0) ? Wq : (proj == 1) ? Wk : Wv;
    float* __restrict__ out     = (proj == 0) ? g_q : (proj == 1) ? g_k : g_v;

    const int tid  = threadIdx.x;
    const int wid  = tid >> 5;
    const int lane = tid & 31;
    const int g    = lane >> 2;
    const int tg   = lane & 3;
    const int wm   = wid & 1;
    const int wn   = wid >> 1;

    const uint32_t smema = (uint32_t)__cvta_generic_to_shared(smem);
    const float* Xb = X + (size_t)mblk * 128 * CC;

    auto issue_chunk = [&](int kc) {
        const uint32_t sAa = smema + (uint32_t)((kc % 3) * STG_FL) * 4;
        const uint32_t sBa = sAa + A_FL * 4;
#pragma unroll
        for (int it = 0; it < 8; it++) {
            int f  = tid + it * 128;
            int r  = f >> 3;
            int c4 = f & 7;
            cp16(sAa + (r * AST + c4 * 4) * 4, Xb + (size_t)r * CC + kc * 32 + c4 * 4);
        }
#pragma unroll
        for (int it = 0; it < 8; it++) {
            int f  = tid + it * 128;
            int r  = f >> 5;
            int c4 = f & 31;
            cp16(sBa + (r * BST + c4 * 4) * 4, W + (size_t)(kc * 32 + r) * HH + c4 * 4);
        }
        cp_commit();
    };

    float acc[4][8][4];
#pragma unroll
    for (int i = 0; i < 4; i++)
#pragma unroll
        for (int n = 0; n < 8; n++)
#pragma unroll
            for (int v = 0; v < 4; v++) acc[i][n][v] = 0.0f;

    issue_chunk(0);
    issue_chunk(1);

    for (int kc = 0; kc < 32; kc++) {
        if (kc < 31) asm volatile("cp.async.wait_group 1;");
        else         asm volatile("cp.async.wait_group 0;");
        __syncthreads();
        if (kc + 2 < 32) issue_chunk(kc + 2);

        const float* aB = smem + (kc % 3) * STG_FL;
        const float* bB = aB + A_FL;

#pragma unroll
        for (int ks = 0; ks < 4; ks++) {
            uint32_t af[4][4];
#pragma unroll
            for (int i = 0; i < 4; i++) {
                const int base = (wm * 64 + i * 16 + g) * AST + ks * 8 + tg;
                af[i][0] = tf32u(aB[base]);
                af[i][1] = tf32u(aB[base + 8 * AST]);
                af[i][2] = tf32u(aB[base + 4]);
                af[i][3] = tf32u(aB[base + 8 * AST + 4]);
            }
#pragma unroll
            for (int n = 0; n < 8; n++) {
                const int base = (ks * 8 + tg) * BST + wn * 64 + n * 8 + g;
                uint32_t b0 = tf32u(bB[base]);
                uint32_t b1 = tf32u(bB[base + 4 * BST]);
#pragma unroll
                for (int i = 0; i < 4; i++)
                    mma8(acc[i][n], af[i], b0, b1);
            }
        }
    }

    const int np = (tg < 2) ? (4 * tg) : (4 * tg - 7);
#pragma unroll
    for (int i = 0; i < 4; i++) {
        const int r0 = mblk * 128 + wm * 64 + i * 16 + g;
#pragma unroll
        for (int n = 0; n < 8; n++) {
            const int gbase = wn * 64 + n * 8;
            float v0 = tf32r(acc[i][n][0]);
            float v1 = tf32r(acc[i][n][1]);
            float v2 = tf32r(acc[i][n][2]);
            float v3 = tf32r(acc[i][n][3]);
            float* d0 = out + (size_t)r0 * HH;
            float* d1 = d0 + 8 * HH;
            if (proj < 2) {
                d0[gbase + np]     = v0;
                d0[gbase + np + 2] = v1;
                d1[gbase + np]     = v2;
                d1[gbase + np + 2] = v3;
            } else {
                *(float2*)(d0 + gbase + 2 * tg) = make_float2(v0, v1);
                *(float2*)(d1 + gbase + 2 * tg) = make_float2(v2, v3);
            }
        }
    }
}

// ---------------------------------------------------------------------------
// Causal flash attention, split-KV, tf32 mma.sync, 2 CTAs/SM, LPT schedule.
// ---------------------------------------------------------------------------
#define KST 136
#define VST 136

__global__ __launch_bounds__(128, 2) void attn_mma_kernel(float* __restrict__ Out)
{
    extern __shared__ float smem_f[];
    float* sQ = smem_f;
    float* sK = sQ + 64 * KST;
    float* sV = sK + 64 * KST;

    const int slot = blockIdx.x >> 3;
    const int b    = blockIdx.x & 7;
    const int qt   = c_qt[slot];
    const int part = c_part[slot];
    const int h    = (qt + 1) >> 1;
    const int j0   = (part == 1) ? h : 0;
    const int j1   = (part == 0) ? h : (qt + 1);

    const int tid  = threadIdx.x;
    const int wid  = tid >> 5;
    const int lane = tid & 31;
    const int g    = lane >> 2;
    const int tg   = lane & 3;

    const uint32_t sQa = (uint32_t)__cvta_generic_to_shared(sQ);
    const uint32_t sKa = (uint32_t)__cvta_generic_to_shared(sK);
    const uint32_t sVa = (uint32_t)__cvta_generic_to_shared(sV);

    const float* Qb = g_q + ((size_t)b * TT + (size_t)qt * 64) * HH;
    const float* Kb = g_k + ((size_t)b * TT + (size_t)j0 * 64) * HH;
    const float* Vb = g_v + ((size_t)b * TT + (size_t)j0 * 64) * HH;

#pragma unroll
    for (int it = 0; it < 16; it++) {
        int f  = tid + it * 128;
        int r  = f >> 5;
        int c4 = f & 31;
        cp16(sQa + (r * KST + c4 * 4) * 4, Qb + r * HH + c4 * 4);
        cp16(sKa + (r * KST + c4 * 4) * 4, Kb + r * HH + c4 * 4);
    }
    cp_commit();
#pragma unroll
    for (int it = 0; it < 16; it++) {
        int f  = tid + it * 128;
        int r  = f >> 5;
        int c4 = f & 31;
        cp16(sVa + (r * VST + c4 * 4) * 4, Vb + r * HH + c4 * 4);
    }
    cp_commit();

    asm volatile("cp.async.wait_group 1;");
    __syncthreads();

    uint32_t qa[16][4];
#pragma unroll
    for (int ks = 0; ks < 16; ks++) {
        const float* qrow = sQ + (16 * wid + g) * KST + ks * 8 + 2 * tg;
        float2 f0 = *(const float2*)qrow;
        float2 f1 = *(const float2*)(qrow + 8 * KST);
        qa[ks][0] = __float_as_uint(f0.x);
        qa[ks][1] = __float_as_uint(f1.x);
        qa[ks][2] = __float_as_uint(f0.y);
        qa[ks][3] = __float_as_uint(f1.y);
    }

    float o[16][4];
#pragma unroll
    for (int n = 0; n < 16; n++)
#pragma unroll
        for (int v = 0; v < 4; v++) o[n][v] = 0.0f;
    float m0 = -1e30f, m1 = -1e30f, l0 = 0.0f, l1 = 0.0f;

    const float SCL = 0.08838834764831845f * 1.4426950408889634f;
    const int src0 = (lane & ~3) | (tg >> 1);
    const int src1 = src0 + 2;
    const bool odd = (tg & 1);

    for (int j = j0; j < j1; j++) {
        if (j > j0) {
            asm volatile("cp.async.wait_group 1;");
            __syncthreads();
        }

        float c[8][4];
#pragma unroll
        for (int n = 0; n < 8; n++)
#pragma unroll
            for (int v = 0; v < 4; v++) c[n][v] = 0.0f;

#pragma unroll
        for (int ks = 0; ks < 16; ks++) {
#pragma unroll
            for (int n = 0; n < 8; n++) {
                float2 kf = *(const float2*)&sK[(n * 8 + g) * KST + ks * 8 + 2 * tg];
                mma8(c[n], qa[ks], __float_as_uint(kf.x), __float_as_uint(kf.y));
            }
        }

        __syncthreads();
        if (j + 1 < j1) {
            const float* Kn = g_k + ((size_t)b * TT + (size_t)(j + 1) * 64) * HH;
#pragma unroll
            for (int it = 0; it < 16; it++) {
                int f  = tid + it * 128;
                int r  = f >> 5;
                int c4 = f & 31;
                cp16(sKa + (r * KST + c4 * 4) * 4, Kn + r * HH + c4 * 4);
            }
            cp_commit();
        }

#pragma unroll
        for (int n = 0; n < 8; n++)
#pragma unroll
            for (int v = 0; v < 4; v++) c[n][v] *= SCL;

        if (j == qt) {
            const int r0 = 16 * wid + g;
            const int r1 = r0 + 8;
#pragma unroll
            for (int n = 0; n < 8; n++) {
                const int col = 8 * n + 2 * tg;
                if (col     > r0) c[n][0] = -1e30f;
                if (col + 1 > r0) c[n][1] = -1e30f;
                if (col     > r1) c[n][2] = -1e30f;
                if (col + 1 > r1) c[n][3] = -1e30f;
            }
        }

        float rm0 = -1e30f, rm1 = -1e30f;
#pragma unroll
        for (int n = 0; n < 8; n++) {
            rm0 = fmaxf(rm0, fmaxf(c[n][0], c[n][1]));
            rm1 = fmaxf(rm1, fmaxf(c[n][2], c[n][3]));
        }
        rm0 = fmaxf(rm0, __shfl_xor_sync(0xffffffffu, rm0, 1));
        rm0 = fmaxf(rm0, __shfl_xor_sync(0xffffffffu, rm0, 2));
        rm1 = fmaxf(rm1, __shfl_xor_sync(0xffffffffu, rm1, 1));
        rm1 = fmaxf(rm1, __shfl_xor_sync(0xffffffffu, rm1, 2));

        const float m0n = fmaxf(m0, rm0);
        const float m1n = fmaxf(m1, rm1);
        const float a0  = fex2(m0 - m0n);
        const float a1  = fex2(m1 - m1n);

        float rs0 = 0.0f, rs1 = 0.0f;
#pragma unroll
        for (int n = 0; n < 8; n++) {
            c[n][0] = fex2(c[n][0] - m0n);
            c[n][1] = fex2(c[n][1] - m0n);
            c[n][2] = fex2(c[n][2] - m1n);
            c[n][3] = fex2(c[n][3] - m1n);
            rs0 += c[n][0] + c[n][1];
            rs1 += c[n][2] + c[n][3];
        }
        rs0 += __shfl_xor_sync(0xffffffffu, rs0, 1);
        rs0 += __shfl_xor_sync(0xffffffffu, rs0, 2);
        rs1 += __shfl_xor_sync(0xffffffffu, rs1, 1);
        rs1 += __shfl_xor_sync(0xffffffffu, rs1, 2);

        l0 = l0 * a0 + rs0;
        l1 = l1 * a1 + rs1;
        m0 = m0n;
        m1 = m1n;

#pragma unroll
        for (int n = 0; n < 16; n++) {
            o[n][0] *= a0; o[n][1] *= a0;
            o[n][2] *= a1; o[n][3] *= a1;
        }

#pragma unroll
        for (int n = 0; n < 8; n++)
#pragma unroll
            for (int v = 0; v < 4; v++) c[n][v] = tf32r(c[n][v]);

        if (j + 1 < j1) asm volatile("cp.async.wait_group 1;");
        else            asm volatile("cp.async.wait_group 0;");
        __syncthreads();

#pragma unroll
        for (int kk = 0; kk < 8; kk++) {
            float v00 = __shfl_sync(0xffffffffu, c[kk][0], src0);
            float v01 = __shfl_sync(0xffffffffu, c[kk][1], src0);
            float v10 = __shfl_sync(0xffffffffu, c[kk][2], src0);
            float v11 = __shfl_sync(0xffffffffu, c[kk][3], src0);
            float v20 = __shfl_sync(0xffffffffu, c[kk][0], src1);
            float v21 = __shfl_sync(0xffffffffu, c[kk][1], src1);
            float v30 = __shfl_sync(0xffffffffu, c[kk][2], src1);
            float v31 = __shfl_sync(0xffffffffu, c[kk][3], src1);
            uint32_t pa[4];
            pa[0] = __float_as_uint(odd ? v01 : v00);
            pa[1] = __float_as_uint(odd ? v11 : v10);
            pa[2] = __float_as_uint(odd ? v21 : v20);
            pa[3] = __float_as_uint(odd ? v31 : v30);
#pragma unroll
            for (int n = 0; n < 16; n++) {
                const int base = (kk * 8 + tg) * VST + 8 * n + g;
                uint32_t b0 = __float_as_uint(sV[base]);
                uint32_t b1 = __float_as_uint(sV[base + 4 * VST]);
                mma8(o[n], pa, b0, b1);
            }
        }

        __syncthreads();
        if (j + 1 < j1) {
            const float* Vn = g_v + ((size_t)b * TT + (size_t)(j + 1) * 64) * HH;
#pragma unroll
            for (int it = 0; it < 16; it++) {
                int f  = tid + it * 128;
                int r  = f >> 5;
                int c4 = f & 31;
                cp16(sVa + (r * VST + c4 * 4) * 4, Vn + r * HH + c4 * 4);
            }
            cp_commit();
        }
    }

    // ----- epilogue -----
    const int r0 = 16 * wid + g;
    if (part == 2) {
        const float inv0 = 1.0f / l0;
        const float inv1 = 1.0f / l1;
        float* p0 = Out + ((size_t)b * TT + qt * 64 + r0) * HH;
        float* p1 = p0 + 8 * HH;
#pragma unroll
        for (int n = 0; n < 16; n++) {
            const int col = 8 * n + 2 * tg;
            *(float2*)(p0 + col) = make_float2(o[n][0] * inv0, o[n][1] * inv0);
            *(float2*)(p1 + col) = make_float2(o[n][2] * inv1, o[n][3] * inv1);
        }
    } else {
        const int pidx = (qt - 16) * 8 + b;
        float* p0 = g_po[part][pidx] + r0 * 128;
        float* p1 = p0 + 8 * 128;
#pragma unroll
        for (int n = 0; n < 16; n++) {
            const int col = 8 * n + 2 * tg;
            *(float2*)(p0 + col) = make_float2(o[n][0], o[n][1]);
            *(float2*)(p1 + col) = make_float2(o[n][2], o[n][3]);
        }
        if (tg == 0) {
            g_pm[part][pidx][r0]     = m0;
            g_pm[part][pidx][r0 + 8] = m1;
            g_pl[part][pidx][r0]     = l0;
            g_pl[part][pidx][r0 + 8] = l1;
        }
    }
}

// ---------------------------------------------------------------------------
// Combine split-KV partials. Grid 512 (4 CTAs per tile, 16 rows each) for TLP.
// ---------------------------------------------------------------------------
__global__ __launch_bounds__(256) void combine_kernel(float* __restrict__ Out)
{
    const int idx  = blockIdx.x >> 2;       // tile
    const int quar = blockIdx.x & 3;        // 16-row quarter
    const int qt   = 16 + (idx >> 3);
    const int b    = idx & 7;
    const int tid  = threadIdx.x;

    const float* O0 = g_po[0][idx];
    const float* O1 = g_po[1][idx];
    const float* M0 = g_pm[0][idx];
    const float* M1 = g_pm[1][idx];
    const float* L0 = g_pl[0][idx];
    const float* L1 = g_pl[1][idx];
    float* dst = Out + ((size_t)b * TT + (size_t)qt * 64) * HH;

#pragma unroll
    for (int it = 0; it < 2; it++) {
        int f  = tid + it * 256;            // 512 float4 in this quarter
        int r  = quar * 16 + (f >> 5);
        int c4 = f & 31;
        float m0v = M0[r], m1v = M1[r];
        float mv  = fmaxf(m0v, m1v);
        float w0  = fex2(m0v - mv);
        float w1  = fex2(m1v - mv);
        float inv = 1.0f / (L0[r] * w0 + L1[r] * w1);
        float4 a  = *(const float4*)(O0 + r * 128 + c4 * 4);
        float4 bb = *(const float4*)(O1 + r * 128 + c4 * 4);
        float4 res = make_float4((a.x * w0 + bb.x * w1) * inv,
                                 (a.y * w0 + bb.y * w1) * inv,
                                 (a.z * w0 + bb.z * w1) * inv,
                                 (a.w * w0 + bb.w * w1) * inv);
        *(float4*)(dst + r * 128 + c4 * 4) = res;
    }
}

// ---------------------------------------------------------------------------
extern "C" void kernel_launch(void* const* d_in, const int* in_sizes, int n_in,
                              void* d_out, int out_size)
{
    const float* x  = (const float*)d_in[0];
    const float* Wq = (const float*)d_in[1];
    const float* Wk = (const float*)d_in[2];
    const float* Wv = (const float*)d_in[3];
    float* out = (float*)d_out;

    (void)in_sizes; (void)n_in; (void)out_size;

    const int gemm_smem = 3 * STG_FL * (int)sizeof(float);
    cudaFuncSetAttribute(qkv_mma_kernel,
                         cudaFuncAttributeMaxDynamicSharedMemorySize, gemm_smem);
    qkv_mma_kernel<<<dim3(3, (BB * TT) / 128), 128, gemm_smem>>>(x, Wq, Wk, Wv);

    const int attn_smem = 64 * (2 * KST + VST) * (int)sizeof(float);
    cudaFuncSetAttribute(attn_mma_kernel,
                         cudaFuncAttributeMaxDynamicSharedMemorySize, attn_smem);
    attn_mma_kernel<<<384, 128, attn_smem>>>(out);

    combine_kernel<<<512, 256>>>(out);
}